// round 10
// baseline (speedup 1.0000x reference)
#include <cuda_runtime.h>
#include <cuda_bf16.h>
#include <cuda_fp16.h>
#include <cstdint>

// Problem constants
#define BW_   256
#define NT_   144
#define DIM_  384
#define H_    12
#define HD_   32
#define NN_   (NT_*NT_)    // 20736
#define TOW_  32
#define TABLE_ 3312
#define QKVN  1152
#define L2E   1.4426950408889634f
#define QS_   (0.17677669529663687f * L2E)

// ---------------- scratch ----------------
__device__ __half g_xh[(size_t)BW_ * NT_ * DIM_];        // 28 MB
__device__ __half g_qkvh[(size_t)BW_ * NT_ * QKVN];      // 85 MB
__device__ __half g_atth[(size_t)BW_ * NT_ * DIM_];      // 28 MB
__device__ unsigned g_wqp[(DIM_/2) * QKVN];              // kp-paired w_qkv (q-scaled)
__device__ unsigned g_wop[(DIM_/2) * DIM_];              // kp-paired w_out
__device__ float g_bqs[QKVN];                            // scaled qkv bias
__device__ unsigned short g_rix[8 * NN_];
__device__ float g_btabT[TOW_ * H_ * TABLE_];            // [t][h][r] * log2e
__device__ float g_maskL[8 * NN_];                       // mask * log2e

// section sizes for the fused prep
#define PREP_X4   ((BW_ * NT_ * DIM_) / 4)       // 3,538,944  <- LARGEST (sets grid)
#define PREP_WQ   ((DIM_/2) * QKVN)              //   221,184
#define PREP_WO   ((DIM_/2) * DIM_)              //    73,728
#define PREP_RM   (8 * NN_)                      //   165,888
#define PREP_BT   (TOW_ * H_ * TABLE_)           // 1,271,808

// ---------------- fused prep: ONE launch, sectioned by idx ----------------
__global__ void prep_all_k(const float* __restrict__ x, const float* __restrict__ w_qkv,
                           const float* __restrict__ b_qkv, const float* __restrict__ w_out,
                           const float* __restrict__ btab, const int* __restrict__ pi,
                           const float* __restrict__ mask,
                           __half* __restrict__ xh, unsigned* __restrict__ wqp,
                           unsigned* __restrict__ wop, float* __restrict__ bqs,
                           unsigned short* __restrict__ rix, float* __restrict__ btabT,
                           float* __restrict__ maskL) {
    const int idx = blockIdx.x * 256 + threadIdx.x;
    if (idx < PREP_X4) {
        float4 v = *(const float4*)(x + 4 * (size_t)idx);
        __half2 a = __floats2half2_rn(v.x, v.y);
        __half2 b = __floats2half2_rn(v.z, v.w);
        *(uint2*)(xh + 4 * (size_t)idx) = make_uint2(*(unsigned*)&a, *(unsigned*)&b);
    }
    if (idx < PREP_WQ) {
        int kp = idx / QKVN, n = idx - kp * QKVN;
        float s = (n < DIM_) ? QS_ : 1.0f;
        __half2 h = __floats2half2_rn(w_qkv[(size_t)(2*kp) * QKVN + n] * s,
                                      w_qkv[(size_t)(2*kp+1) * QKVN + n] * s);
        wqp[idx] = *(unsigned*)&h;
    }
    if (idx < PREP_WO) {
        int kp = idx / DIM_, n = idx - kp * DIM_;
        __half2 h = __floats2half2_rn(w_out[(size_t)(2*kp) * DIM_ + n],
                                      w_out[(size_t)(2*kp+1) * DIM_ + n]);
        wop[idx] = *(unsigned*)&h;
    }
    if (idx < QKVN) bqs[idx] = b_qkv[idx] * ((idx < DIM_) ? QS_ : 1.0f);
    if (idx < PREP_RM) {
        int gw = idx / NN_, ij = idx - gw * NN_;
        rix[idx] = (unsigned short)pi[(ij * 8 + gw) % NN_];
        maskL[idx] = mask[idx] * L2E;
    }
    if (idx < PREP_BT) {
        int th = idx / TABLE_, r = idx - th * TABLE_;
        int t = th / H_, h = th - t * H_;
        btabT[idx] = btab[(r * TOW_ + t) * H_ + h] * L2E;
    }
}

// ---------------- math helpers ----------------
__device__ __forceinline__ float ex2f(float x) {
    float r; asm("ex2.approx.ftz.f32 %0, %1;" : "=f"(r) : "f"(x)); return r;
}
__device__ __forceinline__ unsigned packh2(float a, float b) {
    __half2 h = __floats2half2_rn(a, b);
    return *reinterpret_cast<unsigned*>(&h);
}
__device__ __forceinline__ void mma_f16(float d[4], unsigned a0, unsigned a1,
                                        unsigned a2, unsigned a3,
                                        unsigned b0, unsigned b1) {
    asm volatile(
        "mma.sync.aligned.m16n8k16.row.col.f32.f16.f16.f32 "
        "{%0,%1,%2,%3},{%4,%5,%6,%7},{%8,%9},{%0,%1,%2,%3};"
        : "+f"(d[0]), "+f"(d[1]), "+f"(d[2]), "+f"(d[3])
        : "r"(a0), "r"(a1), "r"(a2), "r"(a3), "r"(b0), "r"(b1));
}
__device__ __forceinline__ void cpa16(unsigned dst, const void* src) {
    asm volatile("cp.async.cg.shared.global [%0], [%1], 16;" :: "r"(dst), "l"(src));
}
#define CPA_COMMIT() asm volatile("cp.async.commit_group;")
#define CPA_WAIT1()  asm volatile("cp.async.wait_group 1;")
#define CPA_WAIT0()  asm volatile("cp.async.wait_group 0;")

// ---------------- GEMM: C = A(half,[M][K]) @ W(kp-paired u32,[K/2][N]) + bias ----
// Tile 256x128, KC=64, 512 threads (16 warps), 3-stage cp.async pipeline.
// As[stage][row(256)][word(32)]: 16B chunk swizzle c ^ (row&7);   32KB/stage
// Bs[stage][kp(32)][word(128)]:  16B chunk swizzle c ^ (2*(kp&3)); 16KB/stage
#define GSM_BYTES (3 * (32768 + 16384))
template<bool HALF_OUT>
__global__ void __launch_bounds__(512, 1)
gemm_cp_k(const __half* __restrict__ A, const unsigned* __restrict__ Bp,
          const float* __restrict__ bias, void* __restrict__ Cv,
          int N, int K) {
    extern __shared__ unsigned smg[];
    unsigned* As = smg;               // [3][8192]
    unsigned* Bs = smg + 3 * 8192;    // [3][4096]
    const unsigned sa_base = (unsigned)__cvta_generic_to_shared(As);
    const unsigned sb_base = (unsigned)__cvta_generic_to_shared(Bs);

    const int tid  = threadIdx.x;
    const int lane = tid & 31;
    const int warp = tid >> 5;              // 0..15
    const int wm = (warp >> 1) * 32;        // 0..224
    const int wn = (warp & 1) * 64;
    const int g = lane >> 2;
    const int t = lane & 3;

    const int m0 = blockIdx.y * 256;
    const int n0 = blockIdx.x * 128;
    const int nch = K / 64;

    float acc[2][8][4];
#pragma unroll
    for (int mt = 0; mt < 2; mt++)
#pragma unroll
        for (int nt = 0; nt < 8; nt++)
#pragma unroll
            for (int i = 0; i < 4; i++) acc[mt][nt][i] = 0.f;

    int bcol[8];
#pragma unroll
    for (int nt = 0; nt < 8; nt++) bcol[nt] = ((wn + nt * 8) ^ (t << 3)) + g;

#define GEMM_ISSUE(stage, ch) do {                                              \
        int kc_ = (ch) * 64;                                                    \
        unsigned ab_ = sa_base + (stage) * 32768;                               \
        unsigned bb_ = sb_base + (stage) * 16384;                               \
        _Pragma("unroll")                                                       \
        for (int p = 0; p < 4; p++) {                                           \
            int idx = tid + p * 512;                                            \
            int r = idx >> 3, g4 = idx & 7;                                     \
            unsigned dst = ab_ + (r * 32 + 4 * (g4 ^ (r & 7))) * 4;             \
            cpa16(dst, A + (size_t)(m0 + r) * K + kc_ + g4 * 8);                \
        }                                                                       \
        _Pragma("unroll")                                                       \
        for (int p = 0; p < 2; p++) {                                           \
            int idx = tid + p * 512;                                            \
            int kp = idx >> 5, g4 = idx & 31;                                   \
            unsigned dst = bb_ + (kp * 128 + 4 * (g4 ^ (2 * (kp & 3)))) * 4;    \
            cpa16(dst, Bp + (size_t)(kc_ / 2 + kp) * N + n0 + g4 * 4);          \
        }                                                                       \
    } while (0)

    GEMM_ISSUE(0, 0); CPA_COMMIT();
    GEMM_ISSUE(1, 1); CPA_COMMIT();

    for (int it = 0; it < nch; it++) {
        if (it + 1 == nch) { CPA_WAIT0(); } else { CPA_WAIT1(); }
        __syncthreads();
        if (it + 2 < nch) { GEMM_ISSUE((it + 2) % 3, it + 2); CPA_COMMIT(); }

        const unsigned* as = As + (it % 3) * 8192;
        const unsigned* bs = Bs + (it % 3) * 4096;
#pragma unroll
        for (int ks = 0; ks < 4; ks++) {
            const int w0 = (8 * ks + t) ^ (g << 2);
            const int w1 = (8 * ks + 4 + t) ^ (g << 2);
            unsigned af[2][4];
#pragma unroll
            for (int mt = 0; mt < 2; mt++) {
                const unsigned* ra = as + (wm + mt * 16 + g) * 32;
                af[mt][0] = ra[w0];
                af[mt][1] = ra[8 * 32 + w0];
                af[mt][2] = ra[w1];
                af[mt][3] = ra[8 * 32 + w1];
            }
            const unsigned* b0r = bs + (8 * ks + t) * 128;
            const unsigned* b1r = bs + (8 * ks + 4 + t) * 128;
#pragma unroll
            for (int nt = 0; nt < 8; nt++) {
                unsigned b0 = b0r[bcol[nt]];
                unsigned b1 = b1r[bcol[nt]];
#pragma unroll
                for (int mt = 0; mt < 2; mt++)
                    mma_f16(acc[mt][nt], af[mt][0], af[mt][1], af[mt][2], af[mt][3], b0, b1);
            }
        }
    }

#pragma unroll
    for (int mt = 0; mt < 2; mt++) {
#pragma unroll
        for (int nt = 0; nt < 8; nt++) {
            int row = m0 + wm + mt * 16 + g;
            int col = n0 + wn + nt * 8 + (t << 1);
            float b0 = __ldg(bias + col);
            float b1 = __ldg(bias + col + 1);
            float v0 = acc[mt][nt][0] + b0, v1 = acc[mt][nt][1] + b1;
            float v2 = acc[mt][nt][2] + b0, v3 = acc[mt][nt][3] + b1;
            if (HALF_OUT) {
                unsigned* C = (unsigned*)Cv;
                C[(size_t)row * (N >> 1) + (col >> 1)] = packh2(v0, v1);
                C[(size_t)(row + 8) * (N >> 1) + (col >> 1)] = packh2(v2, v3);
            } else {
                float* C = (float*)Cv;
                *(float2*)(C + (size_t)row * N + col) = make_float2(v0, v1);
                *(float2*)(C + (size_t)(row + 8) * N + col) = make_float2(v2, v3);
            }
        }
    }
#undef GEMM_ISSUE
}

// ---------------- fused attention: one CTA per (head, window) ----------------
// smem (u32): qh[144*36] | kh[144*36] | vh[72*40] | tcol[3312]
#define QK_STR 36
#define ATT_SMEM_WORDS (5184 + 5184 + 2880 + 3312)
#define ATT_SMEM_BYTES (ATT_SMEM_WORDS * 4)

__global__ void __launch_bounds__(288, 3)
attn_k(const __half* __restrict__ qkvh, const float* __restrict__ maskL,
       const float* __restrict__ btabT, const unsigned short* __restrict__ rix,
       __half* __restrict__ atth) {
    extern __shared__ unsigned sm[];
    unsigned* qh = sm;                       // [144][36]
    unsigned* kh = sm + 5184;                // [144][36]
    unsigned* vh = sm + 10368;               // [72][40]
    float*  tcol = (float*)(sm + 13248);     // [3312]

    const int h   = blockIdx.x;
    const int bw  = blockIdx.y;
    const int tid = threadIdx.x;
    const int lane = tid & 31;
    const int warp = tid >> 5;               // 0..8
    const int g  = lane >> 2;
    const int tq = lane & 3;
    const int r0 = warp * 16;

    const int ti = bw & 31;
    const int gw = bw >> 5;
    const int w  = bw & 7;

    const unsigned* bu = (const unsigned*)qkvh + (size_t)bw * NT_ * 576 + h * 16;

    // ---- stage q,k (pure copies; q pre-scaled in weights) ----
    for (int idx = tid; idx < 576; idx += 288) {
        int n = idx >> 2, s = (idx & 3) << 2;
        const unsigned* p = bu + (size_t)n * 576 + s;
        *(uint4*)(qh + n * QK_STR + s) = *(const uint4*)p;
        *(uint4*)(kh + n * QK_STR + s) = *(const uint4*)(p + 192);
    }
    // ---- stage V paired along tokens ----
    for (int idx = tid; idx < 576; idx += 288) {
        int jp = idx >> 3, s = idx & 7;
        const unsigned* p0 = bu + (size_t)(2 * jp) * 576 + 384 + s * 2;
        uint2 u = *(const uint2*)p0;
        uint2 v = *(const uint2*)(p0 + 576);
        uint4 o;
        o.x = __byte_perm(u.x, v.x, 0x5410);
        o.y = __byte_perm(u.x, v.x, 0x7632);
        o.z = __byte_perm(u.y, v.y, 0x5410);
        o.w = __byte_perm(u.y, v.y, 0x7632);
        *(uint4*)(vh + jp * 40 + s * 4) = o;
    }
    // ---- stage bias column ----
    {
        const float* bt = btabT + (size_t)(ti * H_ + h) * TABLE_;
        for (int r = tid; r < TABLE_; r += 288) tcol[r] = bt[r];
    }
    __syncthreads();

    // ---- per-nt interleaved: S-tile MMA -> bias/mask gather -> exp -> pack ----
    unsigned aq[2][4];
#pragma unroll
    for (int ks = 0; ks < 2; ks++) {
        aq[ks][0] = qh[(r0 + g) * QK_STR + ks * 8 + tq];
        aq[ks][1] = qh[(r0 + g + 8) * QK_STR + ks * 8 + tq];
        aq[ks][2] = qh[(r0 + g) * QK_STR + ks * 8 + tq + 4];
        aq[ks][3] = qh[(r0 + g + 8) * QK_STR + ks * 8 + tq + 4];
    }

    const int ia = r0 + g, ib = r0 + g + 8;
    const unsigned short* rra = rix + gw * NN_ + ia * NT_;
    const unsigned short* rrb = rix + gw * NN_ + ib * NT_;
    const float* mra = maskL + w * NN_ + ia * NT_;
    const float* mrb = maskL + w * NN_ + ib * NT_;

    float sa = 0.f, sb = 0.f;
    uint2 pf[18];
#pragma unroll
    for (int nt = 0; nt < 18; nt++) {
        float acc4[4] = {0.f, 0.f, 0.f, 0.f};
#pragma unroll
        for (int ks = 0; ks < 2; ks++) {
            unsigned b0 = kh[(nt * 8 + g) * QK_STR + ks * 8 + tq];
            unsigned b1 = kh[(nt * 8 + g) * QK_STR + ks * 8 + tq + 4];
            mma_f16(acc4, aq[ks][0], aq[ks][1], aq[ks][2], aq[ks][3], b0, b1);
        }
        int j = nt * 8 + 2 * tq;
        unsigned ra = *(const unsigned*)(rra + j);
        unsigned rb = *(const unsigned*)(rrb + j);
        float2 ma = *(const float2*)(mra + j);
        float2 mb = *(const float2*)(mrb + j);
        float y0 = acc4[0] + tcol[ra & 0xFFFF] + ma.x;
        float y1 = acc4[1] + tcol[ra >> 16]    + ma.y;
        float y2 = acc4[2] + tcol[rb & 0xFFFF] + mb.x;
        float y3 = acc4[3] + tcol[rb >> 16]    + mb.y;
        float e0 = ex2f(y0), e1 = ex2f(y1), e2 = ex2f(y2), e3 = ex2f(y3);
        sa += e0 + e1;
        sb += e2 + e3;
        pf[nt].x = packh2(e0, e1);
        pf[nt].y = packh2(e2, e3);
    }
    sa += __shfl_xor_sync(0xffffffffu, sa, 1);
    sa += __shfl_xor_sync(0xffffffffu, sa, 2);
    sb += __shfl_xor_sync(0xffffffffu, sb, 1);
    sb += __shfl_xor_sync(0xffffffffu, sb, 2);
    const float inva = 1.0f / sa;
    const float invb = 1.0f / sb;

    // ---- O = P @ V (A fragments straight from pf registers) ----
    float o[4][4];
#pragma unroll
    for (int nt = 0; nt < 4; nt++)
#pragma unroll
        for (int i = 0; i < 4; i++) o[nt][i] = 0.f;

#pragma unroll
    for (int kt = 0; kt < 9; kt++) {
        unsigned a0 = pf[2 * kt].x;
        unsigned a1 = pf[2 * kt].y;
        unsigned a2 = pf[2 * kt + 1].x;
        unsigned a3 = pf[2 * kt + 1].y;
#pragma unroll
        for (int nt = 0; nt < 4; nt++) {
            unsigned b0 = vh[(8 * kt + tq) * 40 + nt * 8 + g];
            unsigned b1 = vh[(8 * kt + tq + 4) * 40 + nt * 8 + g];
            mma_f16(o[nt], a0, a1, a2, a3, b0, b1);
        }
    }

    // ---- normalize + store half ----
    unsigned* orow = (unsigned*)atth + (size_t)bw * NT_ * 192 + h * 16;
#pragma unroll
    for (int nt = 0; nt < 4; nt++) {
        int cw = nt * 4 + tq;
        orow[(size_t)ia * 192 + cw] = packh2(o[nt][0] * inva, o[nt][1] * inva);
        orow[(size_t)ib * 192 + cw] = packh2(o[nt][2] * invb, o[nt][3] * invb);
    }
}

// ---------------- launch ----------------
extern "C" void kernel_launch(void* const* d_in, const int* in_sizes, int n_in,
                              void* d_out, int out_size) {
    const float* x        = (const float*)d_in[0];
    const float* mask     = (const float*)d_in[1];
    const float* w_qkv    = (const float*)d_in[2];
    const float* b_qkv    = (const float*)d_in[3];
    const float* w_out    = (const float*)d_in[4];
    const float* b_out    = (const float*)d_in[5];
    const float* btab     = (const float*)d_in[6];
    const int*   pos_idx  = (const int*)d_in[7];
    float* out = (float*)d_out;

    __half *xh, *qkvh, *atth;
    unsigned *wqp, *wop;
    float *bqs, *btabT, *maskL;
    unsigned short* rix;
    cudaGetSymbolAddress((void**)&xh, g_xh);
    cudaGetSymbolAddress((void**)&qkvh, g_qkvh);
    cudaGetSymbolAddress((void**)&atth, g_atth);
    cudaGetSymbolAddress((void**)&wqp, g_wqp);
    cudaGetSymbolAddress((void**)&wop, g_wop);
    cudaGetSymbolAddress((void**)&bqs, g_bqs);
    cudaGetSymbolAddress((void**)&rix, g_rix);
    cudaGetSymbolAddress((void**)&btabT, g_btabT);
    cudaGetSymbolAddress((void**)&maskL, g_maskL);

    cudaFuncSetAttribute(attn_k, cudaFuncAttributeMaxDynamicSharedMemorySize, ATT_SMEM_BYTES);
    cudaFuncSetAttribute(gemm_cp_k<true>,  cudaFuncAttributeMaxDynamicSharedMemorySize, GSM_BYTES);
    cudaFuncSetAttribute(gemm_cp_k<false>, cudaFuncAttributeMaxDynamicSharedMemorySize, GSM_BYTES);

    // fused preprocessing — grid sized by the LARGEST section (x-conversion)
    prep_all_k<<<(PREP_X4 + 255) / 256, 256>>>(
        x, w_qkv, b_qkv, w_out, btab, pos_idx, mask,
        xh, wqp, wop, bqs, rix, btabT, maskL);

    // QKV projection: (36864 x 384) @ (384 x 1152) + b -> half
    gemm_cp_k<true><<<dim3(QKVN / 128, (BW_ * NT_) / 256), 512, GSM_BYTES>>>(
        xh, wqp, bqs, qkvh, QKVN, DIM_);

    // fused attention (3 CTAs/SM)
    attn_k<<<dim3(H_, BW_), 288, ATT_SMEM_BYTES>>>(qkvh, maskL, btabT, rix, atth);

    // output projection: (36864 x 384) @ (384 x 384) + b -> float
    gemm_cp_k<false><<<dim3(DIM_ / 128, (BW_ * NT_) / 256), 512, GSM_BYTES>>>(
        atth, wop, b_out, out, DIM_, DIM_);
}

// round 13
// speedup vs baseline: 1.0407x; 1.0407x over previous
#include <cuda_runtime.h>
#include <cuda_bf16.h>
#include <cuda_fp16.h>
#include <cstdint>

// Problem constants
#define BW_   256
#define NT_   144
#define DIM_  384
#define H_    12
#define HD_   32
#define NN_   (NT_*NT_)    // 20736
#define TOW_  32
#define TABLE_ 3312
#define QKVN  1152
#define L2E   1.4426950408889634f
#define QS_   (0.17677669529663687f * L2E)

// ---------------- scratch ----------------
__device__ __half g_xh[(size_t)BW_ * NT_ * DIM_];        // 28 MB
__device__ __half g_qkvh[(size_t)BW_ * NT_ * QKVN];      // 85 MB
__device__ __half g_atth[(size_t)BW_ * NT_ * DIM_];      // 28 MB
__device__ unsigned g_wqp[(DIM_/2) * QKVN];              // kp-paired w_qkv (q-scaled)
__device__ unsigned g_wop[(DIM_/2) * DIM_];              // kp-paired w_out
__device__ float g_bqs[QKVN];                            // scaled qkv bias
__device__ unsigned short g_rix[8 * NN_];
__device__ float g_btabT[TOW_ * H_ * TABLE_];            // [t][h][r] * log2e
__device__ float g_maskL[8 * NN_];                       // mask * log2e

// section sizes for the fused prep
#define PREP_X4   ((BW_ * NT_ * DIM_) / 4)       // 3,538,944  <- LARGEST (sets grid)
#define PREP_WQ   ((DIM_/2) * QKVN)              //   221,184
#define PREP_WO   ((DIM_/2) * DIM_)              //    73,728
#define PREP_RM   (8 * NN_)                      //   165,888
#define PREP_BT   (TOW_ * H_ * TABLE_)           // 1,271,808

// ---------------- fused prep: ONE launch, sectioned by idx ----------------
__global__ void prep_all_k(const float* __restrict__ x, const float* __restrict__ w_qkv,
                           const float* __restrict__ b_qkv, const float* __restrict__ w_out,
                           const float* __restrict__ btab, const int* __restrict__ pi,
                           const float* __restrict__ mask,
                           __half* __restrict__ xh, unsigned* __restrict__ wqp,
                           unsigned* __restrict__ wop, float* __restrict__ bqs,
                           unsigned short* __restrict__ rix, float* __restrict__ btabT,
                           float* __restrict__ maskL) {
    const int idx = blockIdx.x * 256 + threadIdx.x;
    if (idx < PREP_X4) {
        float4 v = *(const float4*)(x + 4 * (size_t)idx);
        __half2 a = __floats2half2_rn(v.x, v.y);
        __half2 b = __floats2half2_rn(v.z, v.w);
        *(uint2*)(xh + 4 * (size_t)idx) = make_uint2(*(unsigned*)&a, *(unsigned*)&b);
    }
    if (idx < PREP_WQ) {
        int kp = idx / QKVN, n = idx - kp * QKVN;
        float s = (n < DIM_) ? QS_ : 1.0f;
        __half2 h = __floats2half2_rn(w_qkv[(size_t)(2*kp) * QKVN + n] * s,
                                      w_qkv[(size_t)(2*kp+1) * QKVN + n] * s);
        wqp[idx] = *(unsigned*)&h;
    }
    if (idx < PREP_WO) {
        int kp = idx / DIM_, n = idx - kp * DIM_;
        __half2 h = __floats2half2_rn(w_out[(size_t)(2*kp) * DIM_ + n],
                                      w_out[(size_t)(2*kp+1) * DIM_ + n]);
        wop[idx] = *(unsigned*)&h;
    }
    if (idx < QKVN) bqs[idx] = b_qkv[idx] * ((idx < DIM_) ? QS_ : 1.0f);
    if (idx < PREP_RM) {
        int gw = idx / NN_, ij = idx - gw * NN_;
        rix[idx] = (unsigned short)pi[(ij * 8 + gw) % NN_];
        maskL[idx] = mask[idx] * L2E;
    }
    if (idx < PREP_BT) {
        int th = idx / TABLE_, r = idx - th * TABLE_;
        int t = th / H_, h = th - t * H_;
        btabT[idx] = btab[(r * TOW_ + t) * H_ + h] * L2E;
    }
}

// ---------------- math helpers ----------------
__device__ __forceinline__ float ex2f(float x) {
    float r; asm("ex2.approx.ftz.f32 %0, %1;" : "=f"(r) : "f"(x)); return r;
}
__device__ __forceinline__ unsigned packh2(float a, float b) {
    __half2 h = __floats2half2_rn(a, b);
    return *reinterpret_cast<unsigned*>(&h);
}
__device__ __forceinline__ void mma_f16(float d[4], unsigned a0, unsigned a1,
                                        unsigned a2, unsigned a3,
                                        unsigned b0, unsigned b1) {
    asm volatile(
        "mma.sync.aligned.m16n8k16.row.col.f32.f16.f16.f32 "
        "{%0,%1,%2,%3},{%4,%5,%6,%7},{%8,%9},{%0,%1,%2,%3};"
        : "+f"(d[0]), "+f"(d[1]), "+f"(d[2]), "+f"(d[3])
        : "r"(a0), "r"(a1), "r"(a2), "r"(a3), "r"(b0), "r"(b1));
}
__device__ __forceinline__ void cpa16(unsigned dst, const void* src) {
    asm volatile("cp.async.cg.shared.global [%0], [%1], 16;" :: "r"(dst), "l"(src));
}
#define CPA_COMMIT() asm volatile("cp.async.commit_group;")
#define CPA_WAIT1()  asm volatile("cp.async.wait_group 1;")
#define CPA_WAIT0()  asm volatile("cp.async.wait_group 0;")

// ---------------- GEMM: C = A(half,[M][K]) @ W(kp-paired u32,[K/2][N]) + bias ----
// Tile 128x128, KC=64, 256 threads, 3-stage cp.async pipeline. (R9 config)
#define GSM_BYTES (3 * (16384 + 16384))
template<bool HALF_OUT>
__global__ void __launch_bounds__(256, 2)
gemm_cp_k(const __half* __restrict__ A, const unsigned* __restrict__ Bp,
          const float* __restrict__ bias, void* __restrict__ Cv,
          int N, int K) {
    extern __shared__ unsigned smg[];
    unsigned* As = smg;              // [3][4096]
    unsigned* Bs = smg + 3 * 4096;   // [3][4096]
    const unsigned sa_base = (unsigned)__cvta_generic_to_shared(As);
    const unsigned sb_base = (unsigned)__cvta_generic_to_shared(Bs);

    const int tid  = threadIdx.x;
    const int lane = tid & 31;
    const int warp = tid >> 5;
    const int wm = (warp >> 1) * 32;
    const int wn = (warp & 1) * 64;
    const int g = lane >> 2;
    const int t = lane & 3;

    const int m0 = blockIdx.y * 128;
    const int n0 = blockIdx.x * 128;
    const int nch = K / 64;

    float acc[2][8][4];
#pragma unroll
    for (int mt = 0; mt < 2; mt++)
#pragma unroll
        for (int nt = 0; nt < 8; nt++)
#pragma unroll
            for (int i = 0; i < 4; i++) acc[mt][nt][i] = 0.f;

    int bcol[8];
#pragma unroll
    for (int nt = 0; nt < 8; nt++) bcol[nt] = ((wn + nt * 8) ^ (t << 3)) + g;

#define GEMM_ISSUE(stage, ch) do {                                              \
        int kc_ = (ch) * 64;                                                    \
        unsigned ab_ = sa_base + (stage) * 16384;                               \
        unsigned bb_ = sb_base + (stage) * 16384;                               \
        _Pragma("unroll")                                                       \
        for (int p = 0; p < 4; p++) {                                           \
            int idx = tid + p * 256;                                            \
            int r = idx >> 3, g4 = idx & 7;                                     \
            unsigned dst = ab_ + (r * 32 + 4 * (g4 ^ (r & 7))) * 4;             \
            cpa16(dst, A + (size_t)(m0 + r) * K + kc_ + g4 * 8);                \
        }                                                                       \
        _Pragma("unroll")                                                       \
        for (int p = 0; p < 4; p++) {                                           \
            int idx = tid + p * 256;                                            \
            int kp = idx >> 5, g4 = idx & 31;                                   \
            unsigned dst = bb_ + (kp * 128 + 4 * (g4 ^ (2 * (kp & 3)))) * 4;    \
            cpa16(dst, Bp + (size_t)(kc_ / 2 + kp) * N + n0 + g4 * 4);          \
        }                                                                       \
    } while (0)

    GEMM_ISSUE(0, 0); CPA_COMMIT();
    GEMM_ISSUE(1, 1); CPA_COMMIT();

    for (int it = 0; it < nch; it++) {
        if (it + 1 == nch) { CPA_WAIT0(); } else { CPA_WAIT1(); }
        __syncthreads();
        if (it + 2 < nch) { GEMM_ISSUE((it + 2) % 3, it + 2); CPA_COMMIT(); }

        const unsigned* as = As + (it % 3) * 4096;
        const unsigned* bs = Bs + (it % 3) * 4096;
#pragma unroll
        for (int ks = 0; ks < 4; ks++) {
            const int w0 = (8 * ks + t) ^ (g << 2);
            const int w1 = (8 * ks + 4 + t) ^ (g << 2);
            unsigned af[2][4];
#pragma unroll
            for (int mt = 0; mt < 2; mt++) {
                const unsigned* ra = as + (wm + mt * 16 + g) * 32;
                af[mt][0] = ra[w0];
                af[mt][1] = ra[8 * 32 + w0];
                af[mt][2] = ra[w1];
                af[mt][3] = ra[8 * 32 + w1];
            }
            const unsigned* b0r = bs + (8 * ks + t) * 128;
            const unsigned* b1r = bs + (8 * ks + 4 + t) * 128;
#pragma unroll
            for (int nt = 0; nt < 8; nt++) {
                unsigned b0 = b0r[bcol[nt]];
                unsigned b1 = b1r[bcol[nt]];
#pragma unroll
                for (int mt = 0; mt < 2; mt++)
                    mma_f16(acc[mt][nt], af[mt][0], af[mt][1], af[mt][2], af[mt][3], b0, b1);
            }
        }
    }

#pragma unroll
    for (int mt = 0; mt < 2; mt++) {
#pragma unroll
        for (int nt = 0; nt < 8; nt++) {
            int row = m0 + wm + mt * 16 + g;
            int col = n0 + wn + nt * 8 + (t << 1);
            float b0 = __ldg(bias + col);
            float b1 = __ldg(bias + col + 1);
            float v0 = acc[mt][nt][0] + b0, v1 = acc[mt][nt][1] + b1;
            float v2 = acc[mt][nt][2] + b0, v3 = acc[mt][nt][3] + b1;
            if (HALF_OUT) {
                unsigned* C = (unsigned*)Cv;
                C[(size_t)row * (N >> 1) + (col >> 1)] = packh2(v0, v1);
                C[(size_t)(row + 8) * (N >> 1) + (col >> 1)] = packh2(v2, v3);
            } else {
                float* C = (float*)Cv;
                *(float2*)(C + (size_t)row * N + col) = make_float2(v0, v1);
                *(float2*)(C + (size_t)(row + 8) * N + col) = make_float2(v2, v3);
            }
        }
    }
#undef GEMM_ISSUE
}

// ---------------- fused attention: one CTA per (head, window) ----------------
// S and PV fused per kt: pf live state is 2 tiles (4 regs), enabling 3 CTAs/SM.
// smem (u32): qh[144*36] | kh[144*36] | vh[72*40] | tcol[3312]
#define QK_STR 36
#define ATT_SMEM_WORDS (5184 + 5184 + 2880 + 3312)
#define ATT_SMEM_BYTES (ATT_SMEM_WORDS * 4)

__global__ void __launch_bounds__(288, 3)
attn_k(const __half* __restrict__ qkvh, const float* __restrict__ maskL,
       const float* __restrict__ btabT, const unsigned short* __restrict__ rix,
       __half* __restrict__ atth) {
    extern __shared__ unsigned sm[];
    unsigned* qh = sm;                       // [144][36]
    unsigned* kh = sm + 5184;                // [144][36]
    unsigned* vh = sm + 10368;               // [72][40]
    float*  tcol = (float*)(sm + 13248);     // [3312]

    const int h   = blockIdx.x;
    const int bw  = blockIdx.y;
    const int tid = threadIdx.x;
    const int lane = tid & 31;
    const int warp = tid >> 5;               // 0..8
    const int g  = lane >> 2;
    const int tq = lane & 3;
    const int r0 = warp * 16;

    const int ti = bw & 31;
    const int gw = bw >> 5;
    const int w  = bw & 7;

    const unsigned* bu = (const unsigned*)qkvh + (size_t)bw * NT_ * 576 + h * 16;

    // ---- stage q,k (pure copies; q pre-scaled in weights) ----
    for (int idx = tid; idx < 576; idx += 288) {
        int n = idx >> 2, s = (idx & 3) << 2;
        const unsigned* p = bu + (size_t)n * 576 + s;
        *(uint4*)(qh + n * QK_STR + s) = *(const uint4*)p;
        *(uint4*)(kh + n * QK_STR + s) = *(const uint4*)(p + 192);
    }
    // ---- stage V paired along tokens ----
    for (int idx = tid; idx < 576; idx += 288) {
        int jp = idx >> 3, s = idx & 7;
        const unsigned* p0 = bu + (size_t)(2 * jp) * 576 + 384 + s * 2;
        uint2 u = *(const uint2*)p0;
        uint2 v = *(const uint2*)(p0 + 576);
        uint4 o;
        o.x = __byte_perm(u.x, v.x, 0x5410);
        o.y = __byte_perm(u.x, v.x, 0x7632);
        o.z = __byte_perm(u.y, v.y, 0x5410);
        o.w = __byte_perm(u.y, v.y, 0x7632);
        *(uint4*)(vh + jp * 40 + s * 4) = o;
    }
    // ---- stage bias column ----
    {
        const float* bt = btabT + (size_t)(ti * H_ + h) * TABLE_;
        for (int r = tid; r < TABLE_; r += 288) tcol[r] = bt[r];
    }
    __syncthreads();

    // ---- q fragments (loaded once, 8 regs) ----
    unsigned aq[2][4];
#pragma unroll
    for (int ks = 0; ks < 2; ks++) {
        aq[ks][0] = qh[(r0 + g) * QK_STR + ks * 8 + tq];
        aq[ks][1] = qh[(r0 + g + 8) * QK_STR + ks * 8 + tq];
        aq[ks][2] = qh[(r0 + g) * QK_STR + ks * 8 + tq + 4];
        aq[ks][3] = qh[(r0 + g + 8) * QK_STR + ks * 8 + tq + 4];
    }

    const int ia = r0 + g, ib = r0 + g + 8;
    const unsigned short* rra = rix + gw * NN_ + ia * NT_;
    const unsigned short* rrb = rix + gw * NN_ + ib * NT_;
    const float* mra = maskL + w * NN_ + ia * NT_;
    const float* mrb = maskL + w * NN_ + ib * NT_;

    float sa = 0.f, sb = 0.f;
    float o[4][4];
#pragma unroll
    for (int nt = 0; nt < 4; nt++)
#pragma unroll
        for (int i = 0; i < 4; i++) o[nt][i] = 0.f;

    // ---- fused S + PV: per kt compute 2 S-tiles, exp, then 4 PV MMAs ----
#pragma unroll
    for (int kt = 0; kt < 9; kt++) {
        unsigned pa[4];   // PV A-fragment for this kt (the only live P state)
#pragma unroll
        for (int half = 0; half < 2; half++) {
            const int nt = 2 * kt + half;
            float acc4[4] = {0.f, 0.f, 0.f, 0.f};
#pragma unroll
            for (int ks = 0; ks < 2; ks++) {
                unsigned b0 = kh[(nt * 8 + g) * QK_STR + ks * 8 + tq];
                unsigned b1 = kh[(nt * 8 + g) * QK_STR + ks * 8 + tq + 4];
                mma_f16(acc4, aq[ks][0], aq[ks][1], aq[ks][2], aq[ks][3], b0, b1);
            }
            int j = nt * 8 + 2 * tq;
            unsigned ra = *(const unsigned*)(rra + j);
            unsigned rb = *(const unsigned*)(rrb + j);
            float2 ma = *(const float2*)(mra + j);
            float2 mb = *(const float2*)(mrb + j);
            float y0 = acc4[0] + tcol[ra & 0xFFFF] + ma.x;
            float y1 = acc4[1] + tcol[ra >> 16]    + ma.y;
            float y2 = acc4[2] + tcol[rb & 0xFFFF] + mb.x;
            float y3 = acc4[3] + tcol[rb >> 16]    + mb.y;
            float e0 = ex2f(y0), e1 = ex2f(y1), e2 = ex2f(y2), e3 = ex2f(y3);
            sa += e0 + e1;
            sb += e2 + e3;
            pa[2 * half]     = packh2(e0, e1);
            pa[2 * half + 1] = packh2(e2, e3);
        }
        // PV for this kt (consumes pa immediately)
#pragma unroll
        for (int nt2 = 0; nt2 < 4; nt2++) {
            unsigned b0 = vh[(8 * kt + tq) * 40 + nt2 * 8 + g];
            unsigned b1 = vh[(8 * kt + tq + 4) * 40 + nt2 * 8 + g];
            mma_f16(o[nt2], pa[0], pa[1], pa[2], pa[3], b0, b1);
        }
    }

    // ---- row sums + normalize + store half ----
    sa += __shfl_xor_sync(0xffffffffu, sa, 1);
    sa += __shfl_xor_sync(0xffffffffu, sa, 2);
    sb += __shfl_xor_sync(0xffffffffu, sb, 1);
    sb += __shfl_xor_sync(0xffffffffu, sb, 2);
    const float inva = 1.0f / sa;
    const float invb = 1.0f / sb;

    unsigned* orow = (unsigned*)atth + (size_t)bw * NT_ * 192 + h * 16;
#pragma unroll
    for (int nt = 0; nt < 4; nt++) {
        int cw = nt * 4 + tq;
        orow[(size_t)ia * 192 + cw] = packh2(o[nt][0] * inva, o[nt][1] * inva);
        orow[(size_t)ib * 192 + cw] = packh2(o[nt][2] * invb, o[nt][3] * invb);
    }
}

// ---------------- launch ----------------
extern "C" void kernel_launch(void* const* d_in, const int* in_sizes, int n_in,
                              void* d_out, int out_size) {
    const float* x        = (const float*)d_in[0];
    const float* mask     = (const float*)d_in[1];
    const float* w_qkv    = (const float*)d_in[2];
    const float* b_qkv    = (const float*)d_in[3];
    const float* w_out    = (const float*)d_in[4];
    const float* b_out    = (const float*)d_in[5];
    const float* btab     = (const float*)d_in[6];
    const int*   pos_idx  = (const int*)d_in[7];
    float* out = (float*)d_out;

    __half *xh, *qkvh, *atth;
    unsigned *wqp, *wop;
    float *bqs, *btabT, *maskL;
    unsigned short* rix;
    cudaGetSymbolAddress((void**)&xh, g_xh);
    cudaGetSymbolAddress((void**)&qkvh, g_qkvh);
    cudaGetSymbolAddress((void**)&atth, g_atth);
    cudaGetSymbolAddress((void**)&wqp, g_wqp);
    cudaGetSymbolAddress((void**)&wop, g_wop);
    cudaGetSymbolAddress((void**)&bqs, g_bqs);
    cudaGetSymbolAddress((void**)&rix, g_rix);
    cudaGetSymbolAddress((void**)&btabT, g_btabT);
    cudaGetSymbolAddress((void**)&maskL, g_maskL);

    cudaFuncSetAttribute(attn_k, cudaFuncAttributeMaxDynamicSharedMemorySize, ATT_SMEM_BYTES);
    cudaFuncSetAttribute(gemm_cp_k<true>,  cudaFuncAttributeMaxDynamicSharedMemorySize, GSM_BYTES);
    cudaFuncSetAttribute(gemm_cp_k<false>, cudaFuncAttributeMaxDynamicSharedMemorySize, GSM_BYTES);

    // fused preprocessing — grid sized by the LARGEST section (x-conversion)
    prep_all_k<<<(PREP_X4 + 255) / 256, 256>>>(
        x, w_qkv, b_qkv, w_out, btab, pos_idx, mask,
        xh, wqp, wop, bqs, rix, btabT, maskL);

    // QKV projection: (36864 x 384) @ (384 x 1152) + b -> half
    gemm_cp_k<true><<<dim3(QKVN / 128, (BW_ * NT_) / 128), 256, GSM_BYTES>>>(
        xh, wqp, bqs, qkvh, QKVN, DIM_);

    // fused attention (3 CTAs/SM, fused S+PV)
    attn_k<<<dim3(H_, BW_), 288, ATT_SMEM_BYTES>>>(qkvh, maskL, btabT, rix, atth);

    // output projection: (36864 x 384) @ (384 x 384) + b -> float
    gemm_cp_k<false><<<dim3(DIM_ / 128, (BW_ * NT_) / 128), 256, GSM_BYTES>>>(
        atth, wop, b_out, out, DIM_, DIM_);
}

// round 14
// speedup vs baseline: 1.1335x; 1.0892x over previous
#include <cuda_runtime.h>
#include <cuda_bf16.h>
#include <cuda_fp16.h>
#include <cstdint>

// Problem constants
#define BW_   256
#define NT_   144
#define DIM_  384
#define H_    12
#define HD_   32
#define NN_   (NT_*NT_)    // 20736
#define TOW_  32
#define TABLE_ 3312
#define QKVN  1152
#define KP_   (DIM_/2)     // 192 k-pairs for both GEMMs (K=384)
#define L2E   1.4426950408889634f
#define QS_   (0.17677669529663687f * L2E)

// ---------------- scratch ----------------
__device__ __half g_xh[(size_t)BW_ * NT_ * DIM_];        // 28 MB
__device__ __half g_qkvh[(size_t)BW_ * NT_ * QKVN];      // 85 MB
__device__ __half g_atth[(size_t)BW_ * NT_ * DIM_];      // 28 MB
__device__ unsigned g_wqp[QKVN * KP_];                   // n-major kp-paired w_qkv (q-scaled)
__device__ unsigned g_wop[DIM_ * KP_];                   // n-major kp-paired w_out
__device__ float g_bqs[QKVN];                            // scaled qkv bias
__device__ unsigned short g_rix[8 * NN_];
__device__ float g_btabT[TOW_ * H_ * TABLE_];            // [t][h][r] * log2e
__device__ float g_maskL[8 * NN_];                       // mask * log2e

// section sizes for the fused prep
#define PREP_X4   ((BW_ * NT_ * DIM_) / 4)       // 3,538,944  <- LARGEST (sets grid)
#define PREP_WQ   (QKVN * KP_)                   //   221,184
#define PREP_WO   (DIM_ * KP_)                   //    73,728
#define PREP_RM   (8 * NN_)                      //   165,888
#define PREP_BT   (TOW_ * H_ * TABLE_)           // 1,271,808

// ---------------- fused prep: ONE launch, sectioned by idx ----------------
__global__ void prep_all_k(const float* __restrict__ x, const float* __restrict__ w_qkv,
                           const float* __restrict__ b_qkv, const float* __restrict__ w_out,
                           const float* __restrict__ btab, const int* __restrict__ pi,
                           const float* __restrict__ mask,
                           __half* __restrict__ xh, unsigned* __restrict__ wqp,
                           unsigned* __restrict__ wop, float* __restrict__ bqs,
                           unsigned short* __restrict__ rix, float* __restrict__ btabT,
                           float* __restrict__ maskL) {
    const int idx = blockIdx.x * 256 + threadIdx.x;
    if (idx < PREP_X4) {
        float4 v = *(const float4*)(x + 4 * (size_t)idx);
        __half2 a = __floats2half2_rn(v.x, v.y);
        __half2 b = __floats2half2_rn(v.z, v.w);
        *(uint2*)(xh + 4 * (size_t)idx) = make_uint2(*(unsigned*)&a, *(unsigned*)&b);
    }
    // w_qkv n-major kp-paired: wqp[n][kp] = {W[2kp][n], W[2kp+1][n]} * s(n)
    if (idx < PREP_WQ) {
        int n = idx / KP_, kp = idx - n * KP_;
        float s = (n < DIM_) ? QS_ : 1.0f;
        __half2 h = __floats2half2_rn(w_qkv[(size_t)(2*kp) * QKVN + n] * s,
                                      w_qkv[(size_t)(2*kp+1) * QKVN + n] * s);
        wqp[idx] = *(unsigned*)&h;
    }
    // w_out n-major kp-paired
    if (idx < PREP_WO) {
        int n = idx / KP_, kp = idx - n * KP_;
        __half2 h = __floats2half2_rn(w_out[(size_t)(2*kp) * DIM_ + n],
                                      w_out[(size_t)(2*kp+1) * DIM_ + n]);
        wop[idx] = *(unsigned*)&h;
    }
    if (idx < QKVN) bqs[idx] = b_qkv[idx] * ((idx < DIM_) ? QS_ : 1.0f);
    if (idx < PREP_RM) {
        int gw = idx / NN_, ij = idx - gw * NN_;
        rix[idx] = (unsigned short)pi[(ij * 8 + gw) % NN_];
        maskL[idx] = mask[idx] * L2E;
    }
    if (idx < PREP_BT) {
        int th = idx / TABLE_, r = idx - th * TABLE_;
        int t = th / H_, h = th - t * H_;
        btabT[idx] = btab[(r * TOW_ + t) * H_ + h] * L2E;
    }
}

// ---------------- math helpers ----------------
__device__ __forceinline__ float ex2f(float x) {
    float r; asm("ex2.approx.ftz.f32 %0, %1;" : "=f"(r) : "f"(x)); return r;
}
__device__ __forceinline__ unsigned packh2(float a, float b) {
    __half2 h = __floats2half2_rn(a, b);
    return *reinterpret_cast<unsigned*>(&h);
}
__device__ __forceinline__ void mma_f16(float d[4], unsigned a0, unsigned a1,
                                        unsigned a2, unsigned a3,
                                        unsigned b0, unsigned b1) {
    asm volatile(
        "mma.sync.aligned.m16n8k16.row.col.f32.f16.f16.f32 "
        "{%0,%1,%2,%3},{%4,%5,%6,%7},{%8,%9},{%0,%1,%2,%3};"
        : "+f"(d[0]), "+f"(d[1]), "+f"(d[2]), "+f"(d[3])
        : "r"(a0), "r"(a1), "r"(a2), "r"(a3), "r"(b0), "r"(b1));
}
__device__ __forceinline__ void ldsm4(unsigned r[4], unsigned addr) {
    asm volatile("ldmatrix.sync.aligned.m8n8.x4.shared.b16 {%0,%1,%2,%3}, [%4];"
                 : "=r"(r[0]), "=r"(r[1]), "=r"(r[2]), "=r"(r[3]) : "r"(addr));
}
__device__ __forceinline__ void cpa16(unsigned dst, const void* src) {
    asm volatile("cp.async.cg.shared.global [%0], [%1], 16;" :: "r"(dst), "l"(src));
}
#define CPA_COMMIT() asm volatile("cp.async.commit_group;")
#define CPA_WAIT1()  asm volatile("cp.async.wait_group 1;")
#define CPA_WAIT0()  asm volatile("cp.async.wait_group 0;")

// ---------------- GEMM: C = A(half,[M][K]) @ Wn(u32,[N][K/2])^T + bias ----------
// Tile 128x128, KC=64, 256 threads, 3-stage cp.async, ldmatrix fragment loads.
// Both smem tiles: 128 rows x 128B, 16B-chunk swizzle c ^ (row&7).
#define GSM_BYTES (3 * (16384 + 16384))
template<bool HALF_OUT>
__global__ void __launch_bounds__(256, 2)
gemm_cp_k(const __half* __restrict__ A, const unsigned* __restrict__ Wn,
          const float* __restrict__ bias, void* __restrict__ Cv,
          int N, int K) {
    extern __shared__ unsigned smg[];
    const unsigned sa_base = (unsigned)__cvta_generic_to_shared(smg);
    const unsigned sb_base = sa_base + 3 * 16384;

    const int tid  = threadIdx.x;
    const int lane = tid & 31;
    const int warp = tid >> 5;
    const int wm = (warp >> 1) * 32;
    const int wn = (warp & 1) * 64;
    const int g = lane >> 2;
    const int t = lane & 3;

    const int m0 = blockIdx.y * 128;
    const int n0 = blockIdx.x * 128;
    const int nch = K / 64;
    const int kp_tot = K >> 1;

    float acc[2][8][4];
#pragma unroll
    for (int mt = 0; mt < 2; mt++)
#pragma unroll
        for (int nt = 0; nt < 8; nt++)
#pragma unroll
            for (int i = 0; i < 4; i++) acc[mt][nt][i] = 0.f;

    // ldmatrix per-lane invariants
    // A tiles per mt: {(r,c0),(r+8,c0),(r,c1),(r+8,c1)} -> lane: row+=((l>>3)&1)*8, chunk+=(l>>4)
    // B tiles per pair: {(n,c0),(n,c1),(n+8,c0),(n+8,c1)} -> lane: row+=(l>>4)*8, chunk+=((l>>3)&1)
    const int a_ca = lane >> 4;          // A chunk selector
    const int b_cb = (lane >> 3) & 1;    // B chunk selector
    int arow[2], browr[4];
#pragma unroll
    for (int mt = 0; mt < 2; mt++) arow[mt] = wm + mt * 16 + ((lane >> 3) & 1) * 8 + (lane & 7);
#pragma unroll
    for (int pr = 0; pr < 4; pr++) browr[pr] = wn + pr * 16 + (lane >> 4) * 8 + (lane & 7);

#define GEMM_ISSUE(stage, ch) do {                                              \
        int kc_ = (ch) * 64;                                                    \
        unsigned ab_ = sa_base + (stage) * 16384;                               \
        unsigned bb_ = sb_base + (stage) * 16384;                               \
        _Pragma("unroll")                                                       \
        for (int p = 0; p < 4; p++) {                                           \
            int idx = tid + p * 256;                                            \
            int r = idx >> 3, c = idx & 7;                                      \
            unsigned so = (r * 32 + 4 * (c ^ (r & 7))) * 4;                     \
            cpa16(ab_ + so, A + (size_t)(m0 + r) * K + kc_ + c * 8);            \
            cpa16(bb_ + so, Wn + (size_t)(n0 + r) * kp_tot + kc_ / 2 + c * 4);  \
        }                                                                       \
    } while (0)

    GEMM_ISSUE(0, 0); CPA_COMMIT();
    GEMM_ISSUE(1, 1); CPA_COMMIT();

    for (int it = 0; it < nch; it++) {
        if (it + 1 == nch) { CPA_WAIT0(); } else { CPA_WAIT1(); }
        __syncthreads();
        if (it + 2 < nch) { GEMM_ISSUE((it + 2) % 3, it + 2); CPA_COMMIT(); }

        const unsigned ab = sa_base + (it % 3) * 16384;
        const unsigned bb = sb_base + (it % 3) * 16384;
#pragma unroll
        for (int ks = 0; ks < 4; ks++) {
            unsigned af[2][4];
#pragma unroll
            for (int mt = 0; mt < 2; mt++) {
                int ch = (2 * ks + a_ca) ^ (arow[mt] & 7);
                ldsm4(af[mt], ab + arow[mt] * 128 + (ch << 4));
            }
#pragma unroll
            for (int pr = 0; pr < 4; pr++) {
                unsigned bf[4];
                int ch = (2 * ks + b_cb) ^ (browr[pr] & 7);
                ldsm4(bf, bb + browr[pr] * 128 + (ch << 4));
#pragma unroll
                for (int mt = 0; mt < 2; mt++) {
                    mma_f16(acc[mt][2 * pr],     af[mt][0], af[mt][1], af[mt][2], af[mt][3], bf[0], bf[1]);
                    mma_f16(acc[mt][2 * pr + 1], af[mt][0], af[mt][1], af[mt][2], af[mt][3], bf[2], bf[3]);
                }
            }
        }
    }

#pragma unroll
    for (int mt = 0; mt < 2; mt++) {
#pragma unroll
        for (int nt = 0; nt < 8; nt++) {
            int row = m0 + wm + mt * 16 + g;
            int col = n0 + wn + nt * 8 + (t << 1);
            float b0 = __ldg(bias + col);
            float b1 = __ldg(bias + col + 1);
            float v0 = acc[mt][nt][0] + b0, v1 = acc[mt][nt][1] + b1;
            float v2 = acc[mt][nt][2] + b0, v3 = acc[mt][nt][3] + b1;
            if (HALF_OUT) {
                unsigned* C = (unsigned*)Cv;
                C[(size_t)row * (N >> 1) + (col >> 1)] = packh2(v0, v1);
                C[(size_t)(row + 8) * (N >> 1) + (col >> 1)] = packh2(v2, v3);
            } else {
                float* C = (float*)Cv;
                *(float2*)(C + (size_t)row * N + col) = make_float2(v0, v1);
                *(float2*)(C + (size_t)(row + 8) * N + col) = make_float2(v2, v3);
            }
        }
    }
#undef GEMM_ISSUE
}

// ---------------- fused attention: one CTA per (head, window) — R9 exact ------
// smem (u32): qh[144*36] | kh[144*36] | vh[72*40] | tcol[3312]
#define QK_STR 36
#define ATT_SMEM_WORDS (5184 + 5184 + 2880 + 3312)
#define ATT_SMEM_BYTES (ATT_SMEM_WORDS * 4)

__global__ void __launch_bounds__(288, 2)
attn_k(const __half* __restrict__ qkvh, const float* __restrict__ maskL,
       const float* __restrict__ btabT, const unsigned short* __restrict__ rix,
       __half* __restrict__ atth) {
    extern __shared__ unsigned sm[];
    unsigned* qh = sm;                       // [144][36]
    unsigned* kh = sm + 5184;                // [144][36]
    unsigned* vh = sm + 10368;               // [72][40]
    float*  tcol = (float*)(sm + 13248);     // [3312]

    const int h   = blockIdx.x;
    const int bw  = blockIdx.y;
    const int tid = threadIdx.x;
    const int lane = tid & 31;
    const int warp = tid >> 5;               // 0..8
    const int g  = lane >> 2;
    const int tq = lane & 3;
    const int r0 = warp * 16;

    const int ti = bw & 31;
    const int gw = bw >> 5;
    const int w  = bw & 7;

    const unsigned* bu = (const unsigned*)qkvh + (size_t)bw * NT_ * 576 + h * 16;

    for (int idx = tid; idx < 576; idx += 288) {
        int n = idx >> 2, s = (idx & 3) << 2;
        const unsigned* p = bu + (size_t)n * 576 + s;
        *(uint4*)(qh + n * QK_STR + s) = *(const uint4*)p;
        *(uint4*)(kh + n * QK_STR + s) = *(const uint4*)(p + 192);
    }
    for (int idx = tid; idx < 576; idx += 288) {
        int jp = idx >> 3, s = idx & 7;
        const unsigned* p0 = bu + (size_t)(2 * jp) * 576 + 384 + s * 2;
        uint2 u = *(const uint2*)p0;
        uint2 v = *(const uint2*)(p0 + 576);
        uint4 o;
        o.x = __byte_perm(u.x, v.x, 0x5410);
        o.y = __byte_perm(u.x, v.x, 0x7632);
        o.z = __byte_perm(u.y, v.y, 0x5410);
        o.w = __byte_perm(u.y, v.y, 0x7632);
        *(uint4*)(vh + jp * 40 + s * 4) = o;
    }
    {
        const float* bt = btabT + (size_t)(ti * H_ + h) * TABLE_;
        for (int r = tid; r < TABLE_; r += 288) tcol[r] = bt[r];
    }
    __syncthreads();

    unsigned aq[2][4];
#pragma unroll
    for (int ks = 0; ks < 2; ks++) {
        aq[ks][0] = qh[(r0 + g) * QK_STR + ks * 8 + tq];
        aq[ks][1] = qh[(r0 + g + 8) * QK_STR + ks * 8 + tq];
        aq[ks][2] = qh[(r0 + g) * QK_STR + ks * 8 + tq + 4];
        aq[ks][3] = qh[(r0 + g + 8) * QK_STR + ks * 8 + tq + 4];
    }

    const int ia = r0 + g, ib = r0 + g + 8;
    const unsigned short* rra = rix + gw * NN_ + ia * NT_;
    const unsigned short* rrb = rix + gw * NN_ + ib * NT_;
    const float* mra = maskL + w * NN_ + ia * NT_;
    const float* mrb = maskL + w * NN_ + ib * NT_;

    float sa = 0.f, sb = 0.f;
    uint2 pf[18];
#pragma unroll
    for (int nt = 0; nt < 18; nt++) {
        float acc4[4] = {0.f, 0.f, 0.f, 0.f};
#pragma unroll
        for (int ks = 0; ks < 2; ks++) {
            unsigned b0 = kh[(nt * 8 + g) * QK_STR + ks * 8 + tq];
            unsigned b1 = kh[(nt * 8 + g) * QK_STR + ks * 8 + tq + 4];
            mma_f16(acc4, aq[ks][0], aq[ks][1], aq[ks][2], aq[ks][3], b0, b1);
        }
        int j = nt * 8 + 2 * tq;
        unsigned ra = *(const unsigned*)(rra + j);
        unsigned rb = *(const unsigned*)(rrb + j);
        float2 ma = *(const float2*)(mra + j);
        float2 mb = *(const float2*)(mrb + j);
        float y0 = acc4[0] + tcol[ra & 0xFFFF] + ma.x;
        float y1 = acc4[1] + tcol[ra >> 16]    + ma.y;
        float y2 = acc4[2] + tcol[rb & 0xFFFF] + mb.x;
        float y3 = acc4[3] + tcol[rb >> 16]    + mb.y;
        float e0 = ex2f(y0), e1 = ex2f(y1), e2 = ex2f(y2), e3 = ex2f(y3);
        sa += e0 + e1;
        sb += e2 + e3;
        pf[nt].x = packh2(e0, e1);
        pf[nt].y = packh2(e2, e3);
    }
    sa += __shfl_xor_sync(0xffffffffu, sa, 1);
    sa += __shfl_xor_sync(0xffffffffu, sa, 2);
    sb += __shfl_xor_sync(0xffffffffu, sb, 1);
    sb += __shfl_xor_sync(0xffffffffu, sb, 2);
    const float inva = 1.0f / sa;
    const float invb = 1.0f / sb;

    float o[4][4];
#pragma unroll
    for (int nt = 0; nt < 4; nt++)
#pragma unroll
        for (int i = 0; i < 4; i++) o[nt][i] = 0.f;

#pragma unroll
    for (int kt = 0; kt < 9; kt++) {
        unsigned a0 = pf[2 * kt].x;
        unsigned a1 = pf[2 * kt].y;
        unsigned a2 = pf[2 * kt + 1].x;
        unsigned a3 = pf[2 * kt + 1].y;
#pragma unroll
        for (int nt = 0; nt < 4; nt++) {
            unsigned b0 = vh[(8 * kt + tq) * 40 + nt * 8 + g];
            unsigned b1 = vh[(8 * kt + tq + 4) * 40 + nt * 8 + g];
            mma_f16(o[nt], a0, a1, a2, a3, b0, b1);
        }
    }

    unsigned* orow = (unsigned*)atth + (size_t)bw * NT_ * 192 + h * 16;
#pragma unroll
    for (int nt = 0; nt < 4; nt++) {
        int cw = nt * 4 + tq;
        orow[(size_t)ia * 192 + cw] = packh2(o[nt][0] * inva, o[nt][1] * inva);
        orow[(size_t)ib * 192 + cw] = packh2(o[nt][2] * invb, o[nt][3] * invb);
    }
}

// ---------------- launch ----------------
extern "C" void kernel_launch(void* const* d_in, const int* in_sizes, int n_in,
                              void* d_out, int out_size) {
    const float* x        = (const float*)d_in[0];
    const float* mask     = (const float*)d_in[1];
    const float* w_qkv    = (const float*)d_in[2];
    const float* b_qkv    = (const float*)d_in[3];
    const float* w_out    = (const float*)d_in[4];
    const float* b_out    = (const float*)d_in[5];
    const float* btab     = (const float*)d_in[6];
    const int*   pos_idx  = (const int*)d_in[7];
    float* out = (float*)d_out;

    __half *xh, *qkvh, *atth;
    unsigned *wqp, *wop;
    float *bqs, *btabT, *maskL;
    unsigned short* rix;
    cudaGetSymbolAddress((void**)&xh, g_xh);
    cudaGetSymbolAddress((void**)&qkvh, g_qkvh);
    cudaGetSymbolAddress((void**)&atth, g_atth);
    cudaGetSymbolAddress((void**)&wqp, g_wqp);
    cudaGetSymbolAddress((void**)&wop, g_wop);
    cudaGetSymbolAddress((void**)&bqs, g_bqs);
    cudaGetSymbolAddress((void**)&rix, g_rix);
    cudaGetSymbolAddress((void**)&btabT, g_btabT);
    cudaGetSymbolAddress((void**)&maskL, g_maskL);

    cudaFuncSetAttribute(attn_k, cudaFuncAttributeMaxDynamicSharedMemorySize, ATT_SMEM_BYTES);
    cudaFuncSetAttribute(gemm_cp_k<true>,  cudaFuncAttributeMaxDynamicSharedMemorySize, GSM_BYTES);
    cudaFuncSetAttribute(gemm_cp_k<false>, cudaFuncAttributeMaxDynamicSharedMemorySize, GSM_BYTES);

    // fused preprocessing — grid sized by the LARGEST section (x-conversion)
    prep_all_k<<<(PREP_X4 + 255) / 256, 256>>>(
        x, w_qkv, b_qkv, w_out, btab, pos_idx, mask,
        xh, wqp, wop, bqs, rix, btabT, maskL);

    // QKV projection: (36864 x 384) @ (384 x 1152) + b -> half
    gemm_cp_k<true><<<dim3(QKVN / 128, (BW_ * NT_) / 128), 256, GSM_BYTES>>>(
        xh, wqp, bqs, qkvh, QKVN, DIM_);

    // fused attention (R9 config)
    attn_k<<<dim3(H_, BW_), 288, ATT_SMEM_BYTES>>>(qkvh, maskL, btabT, rix, atth);

    // output projection: (36864 x 384) @ (384 x 384) + b -> float
    gemm_cp_k<false><<<dim3(DIM_ / 128, (BW_ * NT_) / 128), 256, GSM_BYTES>>>(
        atth, wop, b_out, out, DIM_, DIM_);
}